// round 16
// baseline (speedup 1.0000x reference)
#include <cuda_runtime.h>
#include <cuda_fp16.h>
#include <cstdint>

#define BB 8192
#define HH 1024
#define KK 1024

// Sc M-split: chunk A = 111 blocks of 64 rows (888 CTAs = 2 exact waves at 3 CTA/SM),
// chunk B = 17 blocks (136 CTAs); final_a overlaps chunk B.
#define MBLK_A 111
#define ROWS_A (MBLK_A * 64)          // 7104
#define MBLK_B (BB / 64 - MBLK_A)     // 17
#define ROWS_B (BB - ROWS_A)          // 1088

// ---------------- scratch (__device__ globals; allocation-free) ----------------
static __device__ __half g_Sr[BB * HH];
static __device__ __half g_Tr[BB * HH];
static __device__ __half g_Su[BB * HH];
static __device__ __half g_Tu[BB * HH];
static __device__ __half g_Tc[BB * HH];
static __device__ __half g_Sc[BB * HH];
static __device__ __half g_Ug[BB * HH];

static __device__ __half g_xh[BB * KK];
static __device__ __half g_hh[BB * HH];
static __device__ __half g_hrh[BB * HH];
static __device__ __half g_Wh[6][HH * KK];

// ---------------- PTX helpers (base ISA only: compute_103-safe) ----------------
__device__ __forceinline__ uint32_t smem_u32(const void* p) {
    uint32_t a;
    asm("{ .reg .u64 t; cvta.to.shared.u64 t, %1; cvt.u32.u64 %0, t; }" : "=r"(a) : "l"(p));
    return a;
}

#define CP_ASYNC16(dst, src) \
    asm volatile("cp.async.cg.shared.global [%0], [%1], 16;" :: "r"(dst), "l"(src))
#define CP_COMMIT() asm volatile("cp.async.commit_group;" ::: "memory")
#define CP_WAIT(n) asm volatile("cp.async.wait_group %0;" :: "n"(n) : "memory")

__device__ __forceinline__ void ldsm_x4(uint32_t* r, uint32_t a) {
    asm volatile("ldmatrix.sync.aligned.m8n8.x4.shared.b16 {%0,%1,%2,%3}, [%4];"
                 : "=r"(r[0]), "=r"(r[1]), "=r"(r[2]), "=r"(r[3]) : "r"(a));
}

__device__ __forceinline__ void mma16816(float* d, const uint32_t* a, const uint32_t* b) {
    asm volatile(
        "mma.sync.aligned.m16n8k16.row.col.f32.f16.f16.f32 "
        "{%0,%1,%2,%3}, {%4,%5,%6,%7}, {%8,%9}, {%0,%1,%2,%3};"
        : "+f"(d[0]), "+f"(d[1]), "+f"(d[2]), "+f"(d[3])
        : "r"(a[0]), "r"(a[1]), "r"(a[2]), "r"(a[3]), "r"(b[0]), "r"(b[1]));
}

#define RSTRIDE 80  // 64B data + 16B pad -> conflict-free ldmatrix phases
#define NCHUNK (KK / 32)  // 32

// ============ Body B: 64x128 tile, warp 32x32, 4 stages, 3 CTA/SM ============
#define B_STAGE (192 * RSTRIDE)          // 15360
#define B_OFF_B (64 * RSTRIDE)
#define B_NST 4
#define GEMM_SMEM_B (B_NST * B_STAGE)    // 61440

struct GemmBatch2 {
    const __half* A[2];
    const __half* B[2];
    __half* C[2];
};

struct GemmBatch3 {
    const __half* A[3];
    const __half* B[3];
    __half* C[3];
};

__device__ __forceinline__ void load_stage_B(
    uint32_t sb, int stage, int kc, int tid, int bm, int bn,
    const __half* __restrict__ A, const __half* __restrict__ B) {
    const uint32_t su = sb + stage * B_STAGE;
    const long kb = (long)kc * 32;
    const int r = tid >> 2;
    const int c16 = tid & 3;

    const char* ga = (const char*)(A + (long)(bm + r) * KK + kb) + c16 * 16;
    const char* gb0 = (const char*)(B + (long)(bn + r) * KK + kb) + c16 * 16;
    const char* gb1 = (const char*)(B + (long)(bn + r + 64) * KK + kb) + c16 * 16;

    CP_ASYNC16(su + r * RSTRIDE + c16 * 16, ga);
    CP_ASYNC16(su + B_OFF_B + r * RSTRIDE + c16 * 16, gb0);
    CP_ASYNC16(su + B_OFF_B + (r + 64) * RSTRIDE + c16 * 16, gb1);
}

__device__ __forceinline__ void gemm_body_B(
    const __half* __restrict__ A, const __half* __restrict__ B, __half* __restrict__ C,
    char* smem) {
    const uint32_t sb = smem_u32(smem);
    const int tid = threadIdx.x;
    const int wid = tid >> 5, lane = tid & 31;
    const int warp_m = wid >> 2, warp_n = wid & 3;
    const int bm = blockIdx.y * 64;
    const int bn = blockIdx.x * 128;

    float acc[2][4][4];
#pragma unroll
    for (int i = 0; i < 2; i++)
#pragma unroll
        for (int j = 0; j < 4; j++)
#pragma unroll
            for (int q = 0; q < 4; q++) acc[i][j][q] = 0.f;

    const uint32_t a_off = (warp_m * 32 + (lane & 15)) * RSTRIDE + (lane >> 4) * 16;
    const uint32_t b_off = B_OFF_B + (warp_n * 32 + (lane & 7)) * RSTRIDE + (lane >> 3) * 16;

#pragma unroll
    for (int s = 0; s < B_NST - 1; s++) {
        load_stage_B(sb, s, s, tid, bm, bn, A, B);
        CP_COMMIT();
    }

    for (int c = 0; c < NCHUNK; c++) {
        CP_WAIT(B_NST - 2);
        __syncthreads();

        if (c + B_NST - 1 < NCHUNK)
            load_stage_B(sb, (c + B_NST - 1) % B_NST, c + B_NST - 1, tid, bm, bn, A, B);
        CP_COMMIT();

        const uint32_t su = sb + (c % B_NST) * B_STAGE;

        uint32_t bb[4][4];
#pragma unroll
        for (int nt = 0; nt < 4; nt++)
            ldsm_x4(bb[nt], su + b_off + nt * 8 * RSTRIDE);
        uint32_t a0[2][4], a1[2][4];
#pragma unroll
        for (int mt = 0; mt < 2; mt++)
            ldsm_x4(a0[mt], su + a_off + mt * 16 * RSTRIDE);
#pragma unroll
        for (int mt = 0; mt < 2; mt++)
            ldsm_x4(a1[mt], su + a_off + mt * 16 * RSTRIDE + 32);

#pragma unroll
        for (int mt = 0; mt < 2; mt++)
#pragma unroll
            for (int nt = 0; nt < 4; nt++) mma16816(acc[mt][nt], a0[mt], &bb[nt][0]);
#pragma unroll
        for (int mt = 0; mt < 2; mt++)
#pragma unroll
            for (int nt = 0; nt < 4; nt++) mma16816(acc[mt][nt], a1[mt], &bb[nt][2]);
    }

    const int gid = lane >> 2, tig = lane & 3;
#pragma unroll
    for (int mt = 0; mt < 2; mt++) {
        const int row0 = bm + warp_m * 32 + mt * 16 + gid;
#pragma unroll
        for (int nt = 0; nt < 4; nt++) {
            const int col = bn + warp_n * 32 + nt * 8 + tig * 2;
            *(__half2*)(C + (long)row0 * HH + col) = __floats2half2_rn(acc[mt][nt][0], acc[mt][nt][1]);
            *(__half2*)(C + (long)(row0 + 8) * HH + col) = __floats2half2_rn(acc[mt][nt][2], acc[mt][nt][3]);
        }
    }
}

__global__ __launch_bounds__(256, 3) void gemm_batched2(GemmBatch2 gb) {
    extern __shared__ char smem[];
    const int z = blockIdx.z;
    gemm_body_B(gb.A[z], gb.B[z], gb.C[z], smem);
}

__global__ __launch_bounds__(256, 3) void gemm_batched3(GemmBatch3 gb) {
    extern __shared__ char smem[];
    const int z = blockIdx.z;
    gemm_body_B(gb.A[z], gb.B[z], gb.C[z], smem);
}

__global__ __launch_bounds__(256, 3) void gemm_single(
    const __half* __restrict__ A, const __half* __restrict__ B, __half* __restrict__ C) {
    extern __shared__ char smem[];
    gemm_body_B(A, B, C, smem);
}

// ---------------- fused fp32 -> fp16 convert ----------------
#define NX4 (BB * KK / 4)
#define NW4 (HH * KK / 4)
#define NTOT4 (2 * NX4 + 6 * NW4)

struct ConvBatch {
    const float4* x;
    const float4* h;
    const float4* W[6];
    uint2* xh;
    uint2* hh;
    uint2* Wh;
};

__global__ __launch_bounds__(256) void tohalf_all(ConvBatch cb) {
    int i = blockIdx.x * blockDim.x + threadIdx.x;
    if (i >= NTOT4) return;
    const float4* src;
    uint2* dst;
    if (i < NX4) {
        src = cb.x + i; dst = cb.xh + i;
    } else if (i < 2 * NX4) {
        int j = i - NX4;
        src = cb.h + j; dst = cb.hh + j;
    } else {
        int j = i - 2 * NX4;
        int w = j / NW4, k = j % NW4;
        src = cb.W[w] + k;
        dst = cb.Wh + (long)w * NW4 + k;
    }
    float4 v = *src;
    __half2 a = __floats2half2_rn(v.x, v.y);
    __half2 b = __floats2half2_rn(v.z, v.w);
    uint2 o;
    o.x = *(uint32_t*)&a;
    o.y = *(uint32_t*)&b;
    *dst = o;
}

// ---------------- reductions ----------------
__device__ __forceinline__ float warp_sum(float v) {
#pragma unroll
    for (int o = 16; o > 0; o >>= 1) v += __shfl_xor_sync(0xffffffffu, v, o);
    return v;
}

__device__ __forceinline__ void block_reduce4(float* p, float* s, int tid) {
    __shared__ float red[4][8];
    const int lane = tid & 31, w = tid >> 5;
#pragma unroll
    for (int q = 0; q < 4; q++) p[q] = warp_sum(p[q]);
    if (lane == 0) {
#pragma unroll
        for (int q = 0; q < 4; q++) red[q][w] = p[q];
    }
    __syncthreads();
    if (tid < 4) {
        float acc = 0.f;
#pragma unroll
        for (int w2 = 0; w2 < 8; w2++) acc += red[tid][w2];
        red[tid][0] = acc;
    }
    __syncthreads();
#pragma unroll
    for (int q = 0; q < 4; q++) s[q] = red[q][0];
}

// fast sigmoid/tanh via __expf (MUFU.EX2; rel err ~1e-6)
__device__ __forceinline__ float fast_sigmoid(float z) {
    return __fdividef(1.0f, 1.0f + __expf(-z));
}
__device__ __forceinline__ float fast_tanh(float z) {
    return __fdividef(2.0f, 1.0f + __expf(-2.0f * z)) - 1.0f;
}

// ---------------- gates_r: r gate only -> HRh (critical path) ----------------
__global__ __launch_bounds__(256) void gates_r_kernel(
    const __half2* __restrict__ Sr, const __half2* __restrict__ Tr,
    const __half2* __restrict__ hh,
    const float* __restrict__ gamma, const float* __restrict__ beta,
    __half2* __restrict__ HRh) {
    const int row = blockIdx.x;
    const int tid = threadIdx.x;
    const long base2 = (long)row * 512;

    float2 vsr[2], vtr[2];
    float p[4];
#pragma unroll
    for (int q = 0; q < 4; q++) p[q] = 0.f;

#pragma unroll
    for (int j = 0; j < 2; j++) {
        const int c2 = tid + j * 256;
        float2 a = __half22float2(Sr[base2 + c2]); vsr[j] = a; p[0] += a.x + a.y; p[1] += a.x * a.x + a.y * a.y;
        float2 b = __half22float2(Tr[base2 + c2]); vtr[j] = b; p[2] += b.x + b.y; p[3] += b.x * b.x + b.y * b.y;
    }

    float s[4];
    block_reduce4(p, s, tid);

    const float inv = 1.0f / (float)HH;
    const float mu0 = s[0] * inv, rs0 = rsqrtf(fmaxf(s[1] * inv - mu0 * mu0, 0.f) + 1e-5f);
    const float mu1 = s[2] * inv, rs1 = rsqrtf(fmaxf(s[3] * inv - mu1 * mu1, 0.f) + 1e-5f);

#pragma unroll
    for (int j = 0; j < 2; j++) {
        const int c2 = tid + j * 256;
        const float2 g0 = *(const float2*)(gamma + 0 * HH + 2 * c2);
        const float2 b0 = *(const float2*)(beta + 0 * HH + 2 * c2);
        const float2 g1 = *(const float2*)(gamma + 1 * HH + 2 * c2);
        const float2 b1 = *(const float2*)(beta + 1 * HH + 2 * c2);
        const float2 hv = __half22float2(hh[base2 + c2]);

        float lnr_x = (vsr[j].x - mu0) * rs0 * g0.x + b0.x + (vtr[j].x - mu1) * rs1 * g1.x + b1.x;
        float lnr_y = (vsr[j].y - mu0) * rs0 * g0.y + b0.y + (vtr[j].y - mu1) * rs1 * g1.y + b1.y;

        float rx = fast_sigmoid(lnr_x), ry = fast_sigmoid(lnr_y);
        HRh[base2 + c2] = __floats2half2_rn(hv.x * rx, hv.y * ry);
    }
}

// ---------------- gates_u: u gate only -> Ug (side branch) ----------------
__global__ __launch_bounds__(256) void gates_u_kernel(
    const __half2* __restrict__ Su, const __half2* __restrict__ Tu,
    const float* __restrict__ gamma, const float* __restrict__ beta,
    __half2* __restrict__ Ug) {
    const int row = blockIdx.x;
    const int tid = threadIdx.x;
    const long base2 = (long)row * 512;

    float2 vsu[2], vtu[2];
    float p[4];
#pragma unroll
    for (int q = 0; q < 4; q++) p[q] = 0.f;

#pragma unroll
    for (int j = 0; j < 2; j++) {
        const int c2 = tid + j * 256;
        float2 d = __half22float2(Su[base2 + c2]); vsu[j] = d; p[0] += d.x + d.y; p[1] += d.x * d.x + d.y * d.y;
        float2 e = __half22float2(Tu[base2 + c2]); vtu[j] = e; p[2] += e.x + e.y; p[3] += e.x * e.x + e.y * e.y;
    }

    float s[4];
    block_reduce4(p, s, tid);

    const float inv = 1.0f / (float)HH;
    const float mu2 = s[0] * inv, rs2 = rsqrtf(fmaxf(s[1] * inv - mu2 * mu2, 0.f) + 1e-5f);
    const float mu3 = s[2] * inv, rs3 = rsqrtf(fmaxf(s[3] * inv - mu3 * mu3, 0.f) + 1e-5f);

#pragma unroll
    for (int j = 0; j < 2; j++) {
        const int c2 = tid + j * 256;
        const float2 g2 = *(const float2*)(gamma + 2 * HH + 2 * c2);
        const float2 b2 = *(const float2*)(beta + 2 * HH + 2 * c2);
        const float2 g3 = *(const float2*)(gamma + 3 * HH + 2 * c2);
        const float2 b3 = *(const float2*)(beta + 3 * HH + 2 * c2);

        float lnu_x = (vsu[j].x - mu2) * rs2 * g2.x + b2.x + (vtu[j].x - mu3) * rs3 * g3.x + b3.x;
        float lnu_y = (vsu[j].y - mu2) * rs2 * g2.y + b2.y + (vtu[j].y - mu3) * rs3 * g3.y + b3.y;

        Ug[base2 + c2] = __floats2half2_rn(fast_sigmoid(lnu_x), fast_sigmoid(lnu_y));
    }
}

// ---------------- final: vectorized half2 (h kept fp32 for output accuracy) ----------------
__global__ __launch_bounds__(256) void final_kernel(
    const __half2* __restrict__ Sc, const __half2* __restrict__ Tc,
    const float2* __restrict__ h, const __half2* __restrict__ Ug,
    const float* __restrict__ gamma, const float* __restrict__ beta,
    float2* __restrict__ out) {
    const int row = blockIdx.x;
    const int tid = threadIdx.x;
    const long base2 = (long)row * 512;

    float2 vsc[2], vtc[2];
    float p[4];
#pragma unroll
    for (int q = 0; q < 4; q++) p[q] = 0.f;

#pragma unroll
    for (int j = 0; j < 2; j++) {
        const int c2 = tid + j * 256;
        float2 a = __half22float2(Sc[base2 + c2]); vsc[j] = a; p[0] += a.x + a.y; p[1] += a.x * a.x + a.y * a.y;
        float2 b = __half22float2(Tc[base2 + c2]); vtc[j] = b; p[2] += b.x + b.y; p[3] += b.x * b.x + b.y * b.y;
    }

    float s[4];
    block_reduce4(p, s, tid);

    const float inv = 1.0f / (float)HH;
    const float mu0 = s[0] * inv, rs0 = rsqrtf(fmaxf(s[1] * inv - mu0 * mu0, 0.f) + 1e-5f);
    const float mu1 = s[2] * inv, rs1 = rsqrtf(fmaxf(s[3] * inv - mu1 * mu1, 0.f) + 1e-5f);

#pragma unroll
    for (int j = 0; j < 2; j++) {
        const int c2 = tid + j * 256;
        const float2 g4 = *(const float2*)(gamma + 4 * HH + 2 * c2);
        const float2 b4 = *(const float2*)(beta + 4 * HH + 2 * c2);
        const float2 g5 = *(const float2*)(gamma + 5 * HH + 2 * c2);
        const float2 b5 = *(const float2*)(beta + 5 * HH + 2 * c2);
        const float2 hv = h[base2 + c2];
        const float2 uv = __half22float2(Ug[base2 + c2]);

        float lnc_x = (vsc[j].x - mu0) * rs0 * g4.x + b4.x + (vtc[j].x - mu1) * rs1 * g5.x + b5.x;
        float lnc_y = (vsc[j].y - mu0) * rs0 * g4.y + b4.y + (vtc[j].y - mu1) * rs1 * g5.y + b5.y;

        float cx = fast_tanh(lnc_x), cy = fast_tanh(lnc_y);
        float2 o;
        o.x = (1.0f - uv.x) * hv.x + uv.x * cx;
        o.y = (1.0f - uv.y) * hv.y + uv.y * cy;
        out[base2 + c2] = o;
    }
}

// ---------------- launch ----------------
extern "C" void kernel_launch(void* const* d_in, const int* in_sizes, int n_in,
                              void* d_out, int out_size) {
    const float* x     = (const float*)d_in[0];
    const float* h     = (const float*)d_in[1];
    const float* W[6]  = {(const float*)d_in[2], (const float*)d_in[3],
                          (const float*)d_in[4], (const float*)d_in[5],
                          (const float*)d_in[6], (const float*)d_in[7]};
    const float* gamma = (const float*)d_in[8];
    const float* beta  = (const float*)d_in[9];
    float* out = (float*)d_out;

    __half *Sr, *Tr, *Su, *Tu, *Tc, *Sc, *Ug;
    cudaGetSymbolAddress((void**)&Sr, g_Sr);
    cudaGetSymbolAddress((void**)&Tr, g_Tr);
    cudaGetSymbolAddress((void**)&Su, g_Su);
    cudaGetSymbolAddress((void**)&Tu, g_Tu);
    cudaGetSymbolAddress((void**)&Tc, g_Tc);
    cudaGetSymbolAddress((void**)&Sc, g_Sc);
    cudaGetSymbolAddress((void**)&Ug, g_Ug);

    __half *xh, *hh, *hrh, *Wh;
    cudaGetSymbolAddress((void**)&xh, g_xh);
    cudaGetSymbolAddress((void**)&hh, g_hh);
    cudaGetSymbolAddress((void**)&hrh, g_hrh);
    cudaGetSymbolAddress((void**)&Wh, g_Wh);

    cudaFuncSetAttribute(gemm_batched2, cudaFuncAttributeMaxDynamicSharedMemorySize, GEMM_SMEM_B);
    cudaFuncSetAttribute(gemm_batched3, cudaFuncAttributeMaxDynamicSharedMemorySize, GEMM_SMEM_B);
    cudaFuncSetAttribute(gemm_single, cudaFuncAttributeMaxDynamicSharedMemorySize, GEMM_SMEM_B);

    // one-time host-side handles (no device memory involved)
    static cudaStream_t s1 = nullptr;
    static cudaEvent_t evConv = nullptr, evU = nullptr, evScA = nullptr;
    if (s1 == nullptr) {
        cudaStreamCreateWithFlags(&s1, cudaStreamNonBlocking);
        cudaEventCreateWithFlags(&evConv, cudaEventDisableTiming);
        cudaEventCreateWithFlags(&evU, cudaEventDisableTiming);
        cudaEventCreateWithFlags(&evScA, cudaEventDisableTiming);
    }

    {
        ConvBatch cb;
        cb.x = (const float4*)x;
        cb.h = (const float4*)h;
        for (int i = 0; i < 6; i++) cb.W[i] = (const float4*)W[i];
        cb.xh = (uint2*)xh;
        cb.hh = (uint2*)hh;
        cb.Wh = (uint2*)Wh;
        tohalf_all<<<(NTOT4 + 255) / 256, 256>>>(cb);
    }

    cudaEventRecord(evConv, 0);
    cudaStreamWaitEvent(s1, evConv, 0);

    // s0 critical path: {Sr, Tr} -> gates_r -> Sc(A,B) -> final_b
    {
        GemmBatch2 gb;
        gb.A[0] = hh; gb.B[0] = Wh + 0L * HH * KK; gb.C[0] = Sr;   // W_r
        gb.A[1] = xh; gb.B[1] = Wh + 1L * HH * KK; gb.C[1] = Tr;   // U_r
        dim3 gg(HH / 128, BB / 64, 2);
        gemm_batched2<<<gg, 256, GEMM_SMEM_B>>>(gb);
    }

    // s1 side branch: {Su, Tu, Tc} -> gates_u -> final_a (after Sc chunk A)
    {
        GemmBatch3 gb;
        gb.A[0] = hh; gb.B[0] = Wh + 2L * HH * KK; gb.C[0] = Su;   // W_u
        gb.A[1] = xh; gb.B[1] = Wh + 3L * HH * KK; gb.C[1] = Tu;   // U_u
        gb.A[2] = xh; gb.B[2] = Wh + 5L * HH * KK; gb.C[2] = Tc;   // U_c
        dim3 gg(HH / 128, BB / 64, 3);
        gemm_batched3<<<gg, 256, GEMM_SMEM_B, s1>>>(gb);
    }

    gates_r_kernel<<<BB, 256>>>((const __half2*)Sr, (const __half2*)Tr,
                                (const __half2*)hh, gamma, beta, (__half2*)hrh);

    gates_u_kernel<<<BB, 256, 0, s1>>>((const __half2*)Su, (const __half2*)Tu,
                                       gamma, beta, (__half2*)Ug);
    cudaEventRecord(evU, s1);

    // Sc chunk A: rows [0, ROWS_A) = 888 CTAs = 2 exact waves
    {
        dim3 gg(HH / 128, MBLK_A);
        gemm_single<<<gg, 256, GEMM_SMEM_B>>>(hrh, Wh + 4L * HH * KK, Sc);
    }
    cudaEventRecord(evScA, 0);

    // Sc chunk B: rows [ROWS_A, BB) = 136 CTAs (~1/3 wave)
    {
        dim3 gg(HH / 128, MBLK_B);
        gemm_single<<<gg, 256, GEMM_SMEM_B>>>(hrh + (long)ROWS_A * KK,
                                              Wh + 4L * HH * KK,
                                              Sc + (long)ROWS_A * HH);
    }

    // final_a on s1: co-runs with Sc chunk B
    cudaStreamWaitEvent(s1, evScA, 0);
    final_kernel<<<ROWS_A, 256, 0, s1>>>((const __half2*)Sc, (const __half2*)Tc,
                                         (const float2*)h, (const __half2*)Ug,
                                         gamma, beta, (float2*)out);
    cudaEventRecord(evU, s1);  // reuse handle: marks final_a done

    // final_b on s0 (needs Ug: s1's gates_u happened before final_a on s1;
    // evU recorded after final_a also orders gates_u)
    cudaStreamWaitEvent(0, evU, 0);
    {
        const long off2 = (long)ROWS_A * 512;
        final_kernel<<<ROWS_B, 256>>>((const __half2*)Sc + off2, (const __half2*)Tc + off2,
                                      (const float2*)h + off2, (const __half2*)Ug + off2,
                                      gamma, beta, (float2*)out + off2);
    }
}

// round 17
// speedup vs baseline: 1.0124x; 1.0124x over previous
#include <cuda_runtime.h>
#include <cuda_fp16.h>
#include <cstdint>

#define BB 8192
#define HH 1024
#define KK 1024

// ---------------- scratch (__device__ globals; allocation-free) ----------------
static __device__ __half g_Sr[BB * HH];
static __device__ __half g_Tr[BB * HH];
static __device__ __half g_Su[BB * HH];
static __device__ __half g_Tu[BB * HH];
static __device__ __half g_Tc[BB * HH];
static __device__ __half g_Sc[BB * HH];
static __device__ __half g_Ug[BB * HH];

static __device__ __half g_xh[BB * KK];
static __device__ __half g_hh[BB * HH];
static __device__ __half g_hrh[BB * HH];
static __device__ __half g_Wh[6][HH * KK];

// ---------------- PTX helpers (base ISA only: compute_103-safe) ----------------
__device__ __forceinline__ uint32_t smem_u32(const void* p) {
    uint32_t a;
    asm("{ .reg .u64 t; cvta.to.shared.u64 t, %1; cvt.u32.u64 %0, t; }" : "=r"(a) : "l"(p));
    return a;
}

#define CP_ASYNC16(dst, src) \
    asm volatile("cp.async.cg.shared.global [%0], [%1], 16;" :: "r"(dst), "l"(src))
#define CP_COMMIT() asm volatile("cp.async.commit_group;" ::: "memory")
#define CP_WAIT(n) asm volatile("cp.async.wait_group %0;" :: "n"(n) : "memory")

__device__ __forceinline__ void ldsm_x4(uint32_t* r, uint32_t a) {
    asm volatile("ldmatrix.sync.aligned.m8n8.x4.shared.b16 {%0,%1,%2,%3}, [%4];"
                 : "=r"(r[0]), "=r"(r[1]), "=r"(r[2]), "=r"(r[3]) : "r"(a));
}

__device__ __forceinline__ void mma16816(float* d, const uint32_t* a, const uint32_t* b) {
    asm volatile(
        "mma.sync.aligned.m16n8k16.row.col.f32.f16.f16.f32 "
        "{%0,%1,%2,%3}, {%4,%5,%6,%7}, {%8,%9}, {%0,%1,%2,%3};"
        : "+f"(d[0]), "+f"(d[1]), "+f"(d[2]), "+f"(d[3])
        : "r"(a[0]), "r"(a[1]), "r"(a[2]), "r"(a[3]), "r"(b[0]), "r"(b[1]));
}

#define RSTRIDE 80  // 64B data + 16B pad -> conflict-free ldmatrix phases
#define NCHUNK (KK / 32)  // 32

// ============ Body B: 64x128 tile, warp 32x32, 4 stages, 3 CTA/SM ============
#define B_STAGE (192 * RSTRIDE)          // 15360
#define B_OFF_B (64 * RSTRIDE)
#define B_NST 4
#define GEMM_SMEM_B (B_NST * B_STAGE)    // 61440

struct GemmBatch2 {
    const __half* A[2];
    const __half* B[2];
    __half* C[2];
};

struct GemmBatch3 {
    const __half* A[3];
    const __half* B[3];
    __half* C[3];
};

__device__ __forceinline__ void load_stage_B(
    uint32_t sb, int stage, int kc, int tid, int bm, int bn,
    const __half* __restrict__ A, const __half* __restrict__ B) {
    const uint32_t su = sb + stage * B_STAGE;
    const long kb = (long)kc * 32;
    const int r = tid >> 2;
    const int c16 = tid & 3;

    const char* ga = (const char*)(A + (long)(bm + r) * KK + kb) + c16 * 16;
    const char* gb0 = (const char*)(B + (long)(bn + r) * KK + kb) + c16 * 16;
    const char* gb1 = (const char*)(B + (long)(bn + r + 64) * KK + kb) + c16 * 16;

    CP_ASYNC16(su + r * RSTRIDE + c16 * 16, ga);
    CP_ASYNC16(su + B_OFF_B + r * RSTRIDE + c16 * 16, gb0);
    CP_ASYNC16(su + B_OFF_B + (r + 64) * RSTRIDE + c16 * 16, gb1);
}

__device__ __forceinline__ void gemm_body_B(
    const __half* __restrict__ A, const __half* __restrict__ B, __half* __restrict__ C,
    char* smem) {
    const uint32_t sb = smem_u32(smem);
    const int tid = threadIdx.x;
    const int wid = tid >> 5, lane = tid & 31;
    const int warp_m = wid >> 2, warp_n = wid & 3;
    const int bm = blockIdx.y * 64;
    const int bn = blockIdx.x * 128;

    float acc[2][4][4];
#pragma unroll
    for (int i = 0; i < 2; i++)
#pragma unroll
        for (int j = 0; j < 4; j++)
#pragma unroll
            for (int q = 0; q < 4; q++) acc[i][j][q] = 0.f;

    const uint32_t a_off = (warp_m * 32 + (lane & 15)) * RSTRIDE + (lane >> 4) * 16;
    const uint32_t b_off = B_OFF_B + (warp_n * 32 + (lane & 7)) * RSTRIDE + (lane >> 3) * 16;

#pragma unroll
    for (int s = 0; s < B_NST - 1; s++) {
        load_stage_B(sb, s, s, tid, bm, bn, A, B);
        CP_COMMIT();
    }

    for (int c = 0; c < NCHUNK; c++) {
        CP_WAIT(B_NST - 2);
        __syncthreads();

        if (c + B_NST - 1 < NCHUNK)
            load_stage_B(sb, (c + B_NST - 1) % B_NST, c + B_NST - 1, tid, bm, bn, A, B);
        CP_COMMIT();

        const uint32_t su = sb + (c % B_NST) * B_STAGE;

        uint32_t bb[4][4];
#pragma unroll
        for (int nt = 0; nt < 4; nt++)
            ldsm_x4(bb[nt], su + b_off + nt * 8 * RSTRIDE);
        uint32_t a0[2][4], a1[2][4];
#pragma unroll
        for (int mt = 0; mt < 2; mt++)
            ldsm_x4(a0[mt], su + a_off + mt * 16 * RSTRIDE);
#pragma unroll
        for (int mt = 0; mt < 2; mt++)
            ldsm_x4(a1[mt], su + a_off + mt * 16 * RSTRIDE + 32);

#pragma unroll
        for (int mt = 0; mt < 2; mt++)
#pragma unroll
            for (int nt = 0; nt < 4; nt++) mma16816(acc[mt][nt], a0[mt], &bb[nt][0]);
#pragma unroll
        for (int mt = 0; mt < 2; mt++)
#pragma unroll
            for (int nt = 0; nt < 4; nt++) mma16816(acc[mt][nt], a1[mt], &bb[nt][2]);
    }

    const int gid = lane >> 2, tig = lane & 3;
#pragma unroll
    for (int mt = 0; mt < 2; mt++) {
        const int row0 = bm + warp_m * 32 + mt * 16 + gid;
#pragma unroll
        for (int nt = 0; nt < 4; nt++) {
            const int col = bn + warp_n * 32 + nt * 8 + tig * 2;
            *(__half2*)(C + (long)row0 * HH + col) = __floats2half2_rn(acc[mt][nt][0], acc[mt][nt][1]);
            *(__half2*)(C + (long)(row0 + 8) * HH + col) = __floats2half2_rn(acc[mt][nt][2], acc[mt][nt][3]);
        }
    }
}

__global__ __launch_bounds__(256, 3) void gemm_batched2(GemmBatch2 gb) {
    extern __shared__ char smem[];
    const int z = blockIdx.z;
    gemm_body_B(gb.A[z], gb.B[z], gb.C[z], smem);
}

__global__ __launch_bounds__(256, 3) void gemm_batched3(GemmBatch3 gb) {
    extern __shared__ char smem[];
    const int z = blockIdx.z;
    gemm_body_B(gb.A[z], gb.B[z], gb.C[z], smem);
}

__global__ __launch_bounds__(256, 3) void gemm_single(
    const __half* __restrict__ A, const __half* __restrict__ B, __half* __restrict__ C) {
    extern __shared__ char smem[];
    gemm_body_B(A, B, C, smem);
}

// ---------------- fused fp32 -> fp16 convert ----------------
#define NX4 (BB * KK / 4)
#define NW4 (HH * KK / 4)
#define NTOT4 (2 * NX4 + 6 * NW4)

struct ConvBatch {
    const float4* x;
    const float4* h;
    const float4* W[6];
    uint2* xh;
    uint2* hh;
    uint2* Wh;
};

__global__ __launch_bounds__(256) void tohalf_all(ConvBatch cb) {
    int i = blockIdx.x * blockDim.x + threadIdx.x;
    if (i >= NTOT4) return;
    const float4* src;
    uint2* dst;
    if (i < NX4) {
        src = cb.x + i; dst = cb.xh + i;
    } else if (i < 2 * NX4) {
        int j = i - NX4;
        src = cb.h + j; dst = cb.hh + j;
    } else {
        int j = i - 2 * NX4;
        int w = j / NW4, k = j % NW4;
        src = cb.W[w] + k;
        dst = cb.Wh + (long)w * NW4 + k;
    }
    float4 v = *src;
    __half2 a = __floats2half2_rn(v.x, v.y);
    __half2 b = __floats2half2_rn(v.z, v.w);
    uint2 o;
    o.x = *(uint32_t*)&a;
    o.y = *(uint32_t*)&b;
    *dst = o;
}

// ---------------- reductions ----------------
__device__ __forceinline__ float warp_sum(float v) {
#pragma unroll
    for (int o = 16; o > 0; o >>= 1) v += __shfl_xor_sync(0xffffffffu, v, o);
    return v;
}

__device__ __forceinline__ void block_reduce4(float* p, float* s, int tid) {
    __shared__ float red[4][8];
    const int lane = tid & 31, w = tid >> 5;
#pragma unroll
    for (int q = 0; q < 4; q++) p[q] = warp_sum(p[q]);
    if (lane == 0) {
#pragma unroll
        for (int q = 0; q < 4; q++) red[q][w] = p[q];
    }
    __syncthreads();
    if (tid < 4) {
        float acc = 0.f;
#pragma unroll
        for (int w2 = 0; w2 < 8; w2++) acc += red[tid][w2];
        red[tid][0] = acc;
    }
    __syncthreads();
#pragma unroll
    for (int q = 0; q < 4; q++) s[q] = red[q][0];
}

// single-MUFU transcendentals via tanh.approx.f32 (sm_75+ base ISA)
__device__ __forceinline__ float fast_tanh(float z) {
    float r;
    asm("tanh.approx.f32 %0, %1;" : "=f"(r) : "f"(z));
    return r;
}
__device__ __forceinline__ float fast_sigmoid(float z) {
    return fmaf(0.5f, fast_tanh(0.5f * z), 0.5f);
}

// ---------------- gates_r: r gate only -> HRh (critical path) ----------------
__global__ __launch_bounds__(256) void gates_r_kernel(
    const __half2* __restrict__ Sr, const __half2* __restrict__ Tr,
    const __half2* __restrict__ hh,
    const float* __restrict__ gamma, const float* __restrict__ beta,
    __half2* __restrict__ HRh) {
    const int row = blockIdx.x;
    const int tid = threadIdx.x;
    const long base2 = (long)row * 512;

    float2 vsr[2], vtr[2];
    float p[4];
#pragma unroll
    for (int q = 0; q < 4; q++) p[q] = 0.f;

#pragma unroll
    for (int j = 0; j < 2; j++) {
        const int c2 = tid + j * 256;
        float2 a = __half22float2(Sr[base2 + c2]); vsr[j] = a; p[0] += a.x + a.y; p[1] += a.x * a.x + a.y * a.y;
        float2 b = __half22float2(Tr[base2 + c2]); vtr[j] = b; p[2] += b.x + b.y; p[3] += b.x * b.x + b.y * b.y;
    }

    float s[4];
    block_reduce4(p, s, tid);

    const float inv = 1.0f / (float)HH;
    const float mu0 = s[0] * inv, rs0 = rsqrtf(fmaxf(s[1] * inv - mu0 * mu0, 0.f) + 1e-5f);
    const float mu1 = s[2] * inv, rs1 = rsqrtf(fmaxf(s[3] * inv - mu1 * mu1, 0.f) + 1e-5f);

#pragma unroll
    for (int j = 0; j < 2; j++) {
        const int c2 = tid + j * 256;
        const float2 g0 = *(const float2*)(gamma + 0 * HH + 2 * c2);
        const float2 b0 = *(const float2*)(beta + 0 * HH + 2 * c2);
        const float2 g1 = *(const float2*)(gamma + 1 * HH + 2 * c2);
        const float2 b1 = *(const float2*)(beta + 1 * HH + 2 * c2);
        const float2 hv = __half22float2(hh[base2 + c2]);

        float lnr_x = (vsr[j].x - mu0) * rs0 * g0.x + b0.x + (vtr[j].x - mu1) * rs1 * g1.x + b1.x;
        float lnr_y = (vsr[j].y - mu0) * rs0 * g0.y + b0.y + (vtr[j].y - mu1) * rs1 * g1.y + b1.y;

        float rx = fast_sigmoid(lnr_x), ry = fast_sigmoid(lnr_y);
        HRh[base2 + c2] = __floats2half2_rn(hv.x * rx, hv.y * ry);
    }
}

// ---------------- gates_u: u gate only -> Ug (side branch) ----------------
__global__ __launch_bounds__(256) void gates_u_kernel(
    const __half2* __restrict__ Su, const __half2* __restrict__ Tu,
    const float* __restrict__ gamma, const float* __restrict__ beta,
    __half2* __restrict__ Ug) {
    const int row = blockIdx.x;
    const int tid = threadIdx.x;
    const long base2 = (long)row * 512;

    float2 vsu[2], vtu[2];
    float p[4];
#pragma unroll
    for (int q = 0; q < 4; q++) p[q] = 0.f;

#pragma unroll
    for (int j = 0; j < 2; j++) {
        const int c2 = tid + j * 256;
        float2 d = __half22float2(Su[base2 + c2]); vsu[j] = d; p[0] += d.x + d.y; p[1] += d.x * d.x + d.y * d.y;
        float2 e = __half22float2(Tu[base2 + c2]); vtu[j] = e; p[2] += e.x + e.y; p[3] += e.x * e.x + e.y * e.y;
    }

    float s[4];
    block_reduce4(p, s, tid);

    const float inv = 1.0f / (float)HH;
    const float mu2 = s[0] * inv, rs2 = rsqrtf(fmaxf(s[1] * inv - mu2 * mu2, 0.f) + 1e-5f);
    const float mu3 = s[2] * inv, rs3 = rsqrtf(fmaxf(s[3] * inv - mu3 * mu3, 0.f) + 1e-5f);

#pragma unroll
    for (int j = 0; j < 2; j++) {
        const int c2 = tid + j * 256;
        const float2 g2 = *(const float2*)(gamma + 2 * HH + 2 * c2);
        const float2 b2 = *(const float2*)(beta + 2 * HH + 2 * c2);
        const float2 g3 = *(const float2*)(gamma + 3 * HH + 2 * c2);
        const float2 b3 = *(const float2*)(beta + 3 * HH + 2 * c2);

        float lnu_x = (vsu[j].x - mu2) * rs2 * g2.x + b2.x + (vtu[j].x - mu3) * rs3 * g3.x + b3.x;
        float lnu_y = (vsu[j].y - mu2) * rs2 * g2.y + b2.y + (vtu[j].y - mu3) * rs3 * g3.y + b3.y;

        Ug[base2 + c2] = __floats2half2_rn(fast_sigmoid(lnu_x), fast_sigmoid(lnu_y));
    }
}

// ---------------- final: vectorized half2 (h kept fp32 for output accuracy) ----------------
__global__ __launch_bounds__(256) void final_kernel(
    const __half2* __restrict__ Sc, const __half2* __restrict__ Tc,
    const float2* __restrict__ h, const __half2* __restrict__ Ug,
    const float* __restrict__ gamma, const float* __restrict__ beta,
    float2* __restrict__ out) {
    const int row = blockIdx.x;
    const int tid = threadIdx.x;
    const long base2 = (long)row * 512;

    float2 vsc[2], vtc[2];
    float p[4];
#pragma unroll
    for (int q = 0; q < 4; q++) p[q] = 0.f;

#pragma unroll
    for (int j = 0; j < 2; j++) {
        const int c2 = tid + j * 256;
        float2 a = __half22float2(Sc[base2 + c2]); vsc[j] = a; p[0] += a.x + a.y; p[1] += a.x * a.x + a.y * a.y;
        float2 b = __half22float2(Tc[base2 + c2]); vtc[j] = b; p[2] += b.x + b.y; p[3] += b.x * b.x + b.y * b.y;
    }

    float s[4];
    block_reduce4(p, s, tid);

    const float inv = 1.0f / (float)HH;
    const float mu0 = s[0] * inv, rs0 = rsqrtf(fmaxf(s[1] * inv - mu0 * mu0, 0.f) + 1e-5f);
    const float mu1 = s[2] * inv, rs1 = rsqrtf(fmaxf(s[3] * inv - mu1 * mu1, 0.f) + 1e-5f);

#pragma unroll
    for (int j = 0; j < 2; j++) {
        const int c2 = tid + j * 256;
        const float2 g4 = *(const float2*)(gamma + 4 * HH + 2 * c2);
        const float2 b4 = *(const float2*)(beta + 4 * HH + 2 * c2);
        const float2 g5 = *(const float2*)(gamma + 5 * HH + 2 * c2);
        const float2 b5 = *(const float2*)(beta + 5 * HH + 2 * c2);
        const float2 hv = h[base2 + c2];
        const float2 uv = __half22float2(Ug[base2 + c2]);

        float lnc_x = (vsc[j].x - mu0) * rs0 * g4.x + b4.x + (vtc[j].x - mu1) * rs1 * g5.x + b5.x;
        float lnc_y = (vsc[j].y - mu0) * rs0 * g4.y + b4.y + (vtc[j].y - mu1) * rs1 * g5.y + b5.y;

        float cx = fast_tanh(lnc_x), cy = fast_tanh(lnc_y);
        float2 o;
        o.x = (1.0f - uv.x) * hv.x + uv.x * cx;
        o.y = (1.0f - uv.y) * hv.y + uv.y * cy;
        out[base2 + c2] = o;
    }
}

// ---------------- launch ----------------
extern "C" void kernel_launch(void* const* d_in, const int* in_sizes, int n_in,
                              void* d_out, int out_size) {
    const float* x     = (const float*)d_in[0];
    const float* h     = (const float*)d_in[1];
    const float* W[6]  = {(const float*)d_in[2], (const float*)d_in[3],
                          (const float*)d_in[4], (const float*)d_in[5],
                          (const float*)d_in[6], (const float*)d_in[7]};
    const float* gamma = (const float*)d_in[8];
    const float* beta  = (const float*)d_in[9];
    float* out = (float*)d_out;

    __half *Sr, *Tr, *Su, *Tu, *Tc, *Sc, *Ug;
    cudaGetSymbolAddress((void**)&Sr, g_Sr);
    cudaGetSymbolAddress((void**)&Tr, g_Tr);
    cudaGetSymbolAddress((void**)&Su, g_Su);
    cudaGetSymbolAddress((void**)&Tu, g_Tu);
    cudaGetSymbolAddress((void**)&Tc, g_Tc);
    cudaGetSymbolAddress((void**)&Sc, g_Sc);
    cudaGetSymbolAddress((void**)&Ug, g_Ug);

    __half *xh, *hh, *hrh, *Wh;
    cudaGetSymbolAddress((void**)&xh, g_xh);
    cudaGetSymbolAddress((void**)&hh, g_hh);
    cudaGetSymbolAddress((void**)&hrh, g_hrh);
    cudaGetSymbolAddress((void**)&Wh, g_Wh);

    cudaFuncSetAttribute(gemm_batched2, cudaFuncAttributeMaxDynamicSharedMemorySize, GEMM_SMEM_B);
    cudaFuncSetAttribute(gemm_batched3, cudaFuncAttributeMaxDynamicSharedMemorySize, GEMM_SMEM_B);
    cudaFuncSetAttribute(gemm_single, cudaFuncAttributeMaxDynamicSharedMemorySize, GEMM_SMEM_B);

    // one-time host-side handles (no device memory involved)
    static cudaStream_t s1 = nullptr;
    static cudaEvent_t evConv = nullptr, evU = nullptr;
    if (s1 == nullptr) {
        cudaStreamCreateWithFlags(&s1, cudaStreamNonBlocking);
        cudaEventCreateWithFlags(&evConv, cudaEventDisableTiming);
        cudaEventCreateWithFlags(&evU, cudaEventDisableTiming);
    }

    {
        ConvBatch cb;
        cb.x = (const float4*)x;
        cb.h = (const float4*)h;
        for (int i = 0; i < 6; i++) cb.W[i] = (const float4*)W[i];
        cb.xh = (uint2*)xh;
        cb.hh = (uint2*)hh;
        cb.Wh = (uint2*)Wh;
        tohalf_all<<<(NTOT4 + 255) / 256, 256>>>(cb);
    }

    cudaEventRecord(evConv, 0);
    cudaStreamWaitEvent(s1, evConv, 0);

    // s1 side branch FIRST (longer pole gets wave-front priority):
    // {Su, Tu, Tc} -> gates_u
    {
        GemmBatch3 gb;
        gb.A[0] = hh; gb.B[0] = Wh + 2L * HH * KK; gb.C[0] = Su;   // W_u
        gb.A[1] = xh; gb.B[1] = Wh + 3L * HH * KK; gb.C[1] = Tu;   // U_u
        gb.A[2] = xh; gb.B[2] = Wh + 5L * HH * KK; gb.C[2] = Tc;   // U_c
        dim3 gg(HH / 128, BB / 64, 3);
        gemm_batched3<<<gg, 256, GEMM_SMEM_B, s1>>>(gb);
    }

    // s0 critical path: {Sr, Tr} -> gates_r -> Sc -> final
    {
        GemmBatch2 gb;
        gb.A[0] = hh; gb.B[0] = Wh + 0L * HH * KK; gb.C[0] = Sr;   // W_r
        gb.A[1] = xh; gb.B[1] = Wh + 1L * HH * KK; gb.C[1] = Tr;   // U_r
        dim3 gg(HH / 128, BB / 64, 2);
        gemm_batched2<<<gg, 256, GEMM_SMEM_B>>>(gb);
    }

    gates_r_kernel<<<BB, 256>>>((const __half2*)Sr, (const __half2*)Tr,
                                (const __half2*)hh, gamma, beta, (__half2*)hrh);

    gates_u_kernel<<<BB, 256, 0, s1>>>((const __half2*)Su, (const __half2*)Tu,
                                       gamma, beta, (__half2*)Ug);
    cudaEventRecord(evU, s1);

    {
        dim3 gg(HH / 128, BB / 64);
        gemm_single<<<gg, 256, GEMM_SMEM_B>>>(hrh, Wh + 4L * HH * KK, Sc);  // W_c
    }

    cudaStreamWaitEvent(0, evU, 0);
    final_kernel<<<BB, 256>>>((const __half2*)Sc, (const __half2*)Tc,
                              (const float2*)h, (const __half2*)Ug,
                              gamma, beta, (float2*)out);
}